// round 1
// baseline (speedup 1.0000x reference)
#include <cuda_runtime.h>
#include <cuda_bf16.h>
#include <math.h>

// Problem constants (fixed by setup_inputs)
#define KK   64
#define DD   320
#define NN   2048
#define MM   128
#define SS   (KK * MM)        // 8192 segments
#define CHUNK 64              // dims per privatized scatter block
#define NCHUNK (DD / CHUNK)   // 5
#define EPSN 1e-12f

// ---------------- device scratch (no allocations allowed) ----------------
__device__ float g_counts[SS];
__device__ int   g_cls[SS];
__device__ float g_a[SS];       // weight[s] * inv_norm[s] * cls  (for v = cm^T a)
__device__ float g_b[SS];       // inv_norm[s] * cls              (for sim_score)
__device__ float g_v[DD];
__device__ int   g_maxsize_bits;
__device__ float g_mean_score;

// ---------------- Z: zero the cross-kernel accumulators ----------------
__global__ void k_zero() {
    int t = threadIdx.x;
    if (t < DD) g_v[t] = 0.0f;
    if (t == 0) g_maxsize_bits = 0;   // bits of +0.0f
}

// ---------------- A: per-cloud counts / label sums / class mask ----------------
__global__ void k_counts(const float* __restrict__ label,
                         const int*   __restrict__ clab) {
    __shared__ float s_cnt[MM];
    __shared__ float s_lbl[MM];
    int k = blockIdx.x;
    int tid = threadIdx.x;
    if (tid < MM) { s_cnt[tid] = 0.0f; s_lbl[tid] = 0.0f; }
    __syncthreads();
    const int base = k * NN;
    for (int n = tid; n < NN; n += blockDim.x) {
        int cid = clab[base + n];
        atomicAdd(&s_cnt[cid], 1.0f);
        atomicAdd(&s_lbl[cid], label[base + n]);
    }
    __syncthreads();
    if (tid < MM) {
        int s = k * MM + tid;
        float c  = s_cnt[tid];
        float dn = fmaxf(c, 1.0f);
        float lm = s_lbl[tid] / dn;
        int cls  = (lm > 0.5f) && (c > 0.0f);
        g_counts[s] = c;
        g_cls[s]    = cls;
        float size  = cls ? c : 0.0f;
        // non-negative floats -> int-bit compare is monotonic
        atomicMax(&g_maxsize_bits, __float_as_int(size));
    }
}

// ---------------- B: privatized feature scatter -> cluster_means ----------------
// grid = KK * NCHUNK blocks; block (256 threads) owns cloud k, dims [dbase, dbase+64)
__global__ __launch_bounds__(256)
void k_scatter(const float* __restrict__ feat,
               const int*   __restrict__ clab,
               float*       __restrict__ out_cm) {
    __shared__ float s_acc[CHUNK * MM];   // [dd][cid] : 32 KB
    __shared__ int   s_cid[NN];           // 8 KB
    int k     = blockIdx.x / NCHUNK;
    int dbase = (blockIdx.x % NCHUNK) * CHUNK;
    int tid   = threadIdx.x;
    int tx    = tid & 31;     // lane -> point index (coalesced along N)
    int ty    = tid >> 5;     // warp -> dim group

    for (int i = tid; i < CHUNK * MM; i += 256) s_acc[i] = 0.0f;
    for (int i = tid; i < NN; i += 256) s_cid[i] = clab[k * NN + i];
    __syncthreads();

    const float* fbase = feat + (size_t)k * DD * NN + (size_t)dbase * NN;
    for (int n0 = 0; n0 < NN; n0 += 32) {
        int n   = n0 + tx;
        int cid = s_cid[n];
        #pragma unroll
        for (int g = 0; g < CHUNK / 8; ++g) {
            int dd = g * 8 + ty;
            float val = fbase[(size_t)dd * NN + n];
            atomicAdd(&s_acc[dd * MM + cid], val);
        }
    }
    __syncthreads();

    // exclusive write-out of this (k, chunk) tile of cluster_means
    for (int i = tid; i < CHUNK * MM; i += 256) {
        int cid = i >> 6;          // i / CHUNK
        int dd  = i & (CHUNK - 1);
        int s   = k * MM + cid;
        float dn = fmaxf(g_counts[s], 1.0f);
        out_cm[(size_t)s * DD + dbase + dd] = s_acc[dd * MM + cid] / dn;
    }
}

// ---------------- C1: per-segment norm -> scale factors ----------------
__global__ void k_norms(const float* __restrict__ cm) {
    int warp = (blockIdx.x * blockDim.x + threadIdx.x) >> 5;
    int lane = threadIdx.x & 31;
    if (warp >= SS) return;
    const float* row = cm + (size_t)warp * DD;
    float ss = 0.0f;
    #pragma unroll
    for (int i = lane; i < DD; i += 32) { float x = row[i]; ss += x * x; }
    #pragma unroll
    for (int o = 16; o > 0; o >>= 1) ss += __shfl_xor_sync(0xffffffffu, ss, o);
    if (lane == 0) {
        float invn = 1.0f / fmaxf(sqrtf(ss), EPSN);
        int cls = g_cls[warp];
        float maxden = fmaxf(__int_as_float(g_maxsize_bits), 1.0f);
        float w = cls ? (g_counts[warp] / maxden) : 0.0f;
        g_a[warp] = cls ? invn * w : 0.0f;
        g_b[warp] = cls ? invn : 0.0f;
    }
}

// ---------------- C2: v = cm^T a  (tiled column reduction) ----------------
// grid = SS/256 blocks of 256 threads; each block handles 256 rows.
__global__ __launch_bounds__(256)
void k_matvec_t(const float* __restrict__ cm) {
    __shared__ float s_a[256];
    int tid = threadIdx.x;
    int s0  = blockIdx.x * 256;
    s_a[tid] = g_a[s0 + tid];
    __syncthreads();
    float acc0 = 0.0f, acc1 = 0.0f;
    for (int r = 0; r < 256; ++r) {
        float av = s_a[r];
        if (av != 0.0f) {                       // uniform branch, skips ~half
            const float* row = cm + (size_t)(s0 + r) * DD;
            acc0 += row[tid] * av;
            if (tid < DD - 256) acc1 += row[256 + tid] * av;
        }
    }
    atomicAdd(&g_v[tid], acc0);
    if (tid < DD - 256) atomicAdd(&g_v[256 + tid], acc1);
}

// ---------------- D: sim_score[s] = b[s] * (cm[s] . v) ----------------
__global__ void k_sim(const float* __restrict__ cm,
                      float* __restrict__ out_sim) {
    int warp = (blockIdx.x * blockDim.x + threadIdx.x) >> 5;
    int lane = threadIdx.x & 31;
    if (warp >= SS) return;
    const float* row = cm + (size_t)warp * DD;
    float dot = 0.0f;
    #pragma unroll
    for (int i = lane; i < DD; i += 32) dot += row[i] * g_v[i];
    #pragma unroll
    for (int o = 16; o > 0; o >>= 1) dot += __shfl_xor_sync(0xffffffffu, dot, o);
    if (lane == 0) out_sim[warp] = g_b[warp] * dot;
}

// ---------------- E1: deterministic mean over class segments ----------------
__global__ void k_mean(const float* __restrict__ sim) {
    __shared__ float s_sum[256];
    __shared__ float s_cnt[256];
    int tid = threadIdx.x;
    float sum = 0.0f, cnt = 0.0f;
    for (int s = tid; s < SS; s += 256) {
        if (g_cls[s]) { sum += sim[s]; cnt += 1.0f; }
    }
    s_sum[tid] = sum; s_cnt[tid] = cnt;
    __syncthreads();
    for (int o = 128; o > 0; o >>= 1) {
        if (tid < o) { s_sum[tid] += s_sum[tid + o]; s_cnt[tid] += s_cnt[tid + o]; }
        __syncthreads();
    }
    if (tid == 0) g_mean_score = s_sum[0] / fmaxf(s_cnt[0], 1.0f);
}

// ---------------- E2: clean mask ----------------
__global__ void k_clean(const float* __restrict__ sim,
                        float* __restrict__ out_clean) {
    int s = blockIdx.x * blockDim.x + threadIdx.x;
    if (s >= SS) return;
    float m = g_mean_score;
    out_clean[s] = ((sim[s] > m) && g_cls[s]) ? 1.0f : 0.0f;
}

// ---------------- launch ----------------
extern "C" void kernel_launch(void* const* d_in, const int* in_sizes, int n_in,
                              void* d_out, int out_size) {
    const float* feat  = (const float*)d_in[0];
    const float* label = (const float*)d_in[1];
    const int*   clab  = (const int*)d_in[2];
    float* out = (float*)d_out;
    float* out_cm    = out;                         // (S, D)
    float* out_sim   = out + (size_t)SS * DD;       // (S,)
    float* out_clean = out + (size_t)SS * DD + SS;  // (S,)

    k_zero<<<1, 320>>>();
    k_counts<<<KK, 256>>>(label, clab);
    k_scatter<<<KK * NCHUNK, 256>>>(feat, clab, out_cm);
    k_norms<<<(SS * 32 + 255) / 256, 256>>>(out_cm);
    k_matvec_t<<<SS / 256, 256>>>(out_cm);
    k_sim<<<(SS * 32 + 255) / 256, 256>>>(out_cm, out_sim);
    k_mean<<<1, 256>>>(out_sim);
    k_clean<<<SS / 256, 256>>>(out_sim, out_clean);
}

// round 2
// speedup vs baseline: 2.1896x; 2.1896x over previous
#include <cuda_runtime.h>
#include <cuda_bf16.h>
#include <math.h>

// Problem constants (fixed by setup_inputs)
#define KK   64
#define DD   320
#define NN   2048
#define MM   128
#define SS   (KK * MM)        // 8192 segments
#define DB   4                // dims per gather block
#define NB   (DD / DB)        // 80 dim-chunks
#define EPSN 1e-12f

// ---------------- device scratch (no allocations allowed) ----------------
__device__ float g_counts[SS];
__device__ int   g_cls[SS];
__device__ float g_a[SS];            // weight * inv_norm * cls
__device__ float g_b[SS];            // inv_norm * cls
__device__ float g_v[DD];
__device__ int   g_maxsize_bits;
__device__ float g_mean_score;
__device__ int   g_off[SS];          // per-cloud exclusive prefix of cluster counts
__device__ int   g_perm[KK * NN];    // counting-sort permutation per cloud

// ---------------- Z: zero cross-kernel accumulators ----------------
__global__ void k_zero() {
    int t = threadIdx.x;
    if (t < DD) g_v[t] = 0.0f;
    if (t == 0) g_maxsize_bits = 0;
}

// ---------------- A: counts / label sums / class mask / offsets / perm ----------------
__global__ __launch_bounds__(256)
void k_counts(const float* __restrict__ label,
              const int*   __restrict__ clab) {
    __shared__ float s_cnt[MM];
    __shared__ float s_lbl[MM];
    __shared__ int   s_off[MM];
    __shared__ int   s_cur[MM];
    int k = blockIdx.x;
    int tid = threadIdx.x;
    if (tid < MM) { s_cnt[tid] = 0.0f; s_lbl[tid] = 0.0f; }
    __syncthreads();
    const int base = k * NN;
    for (int n = tid; n < NN; n += 256) {
        int cid = clab[base + n];
        atomicAdd(&s_cnt[cid], 1.0f);
        atomicAdd(&s_lbl[cid], label[base + n]);
    }
    __syncthreads();
    if (tid == 0) {                      // serial 128-wide scan: ~trivial
        int acc = 0;
        for (int m = 0; m < MM; ++m) { s_off[m] = acc; acc += (int)s_cnt[m]; }
    }
    __syncthreads();
    if (tid < MM) {
        int s = k * MM + tid;
        float c  = s_cnt[tid];
        float dn = fmaxf(c, 1.0f);
        float lm = s_lbl[tid] / dn;
        int cls  = (lm > 0.5f) && (c > 0.0f);
        g_counts[s] = c;
        g_cls[s]    = cls;
        g_off[s]    = s_off[tid];
        s_cur[tid]  = s_off[tid];
        float size  = cls ? c : 0.0f;
        atomicMax(&g_maxsize_bits, __float_as_int(size));  // monotone for non-neg floats
    }
    __syncthreads();
    for (int n = tid; n < NN; n += 256) {
        int cid = clab[base + n];
        int pos = atomicAdd(&s_cur[cid], 1);
        g_perm[base + pos] = n;
    }
}

// ---------------- B: staged gather -> cluster_means (NO atomics) ----------------
// grid = KK*NB blocks, 128 threads; block owns (cloud k, dims [dbase,dbase+4))
__global__ __launch_bounds__(128)
void k_gather(const float* __restrict__ feat,
              float*       __restrict__ out_cm) {
    __shared__ float s_feat[DB * NN];   // 32 KB
    __shared__ int   s_perm[NN];        // 8 KB
    __shared__ int   s_off[MM + 1];
    int k     = blockIdx.x / NB;
    int dbase = (blockIdx.x % NB) * DB;
    int tid   = threadIdx.x;

    // stage perm (coalesced int4)
    const int4* pg = (const int4*)(g_perm + k * NN);
    for (int i = tid; i < NN / 4; i += 128) ((int4*)s_perm)[i] = pg[i];
    if (tid < MM) s_off[tid] = g_off[k * MM + tid];
    if (tid == 0) s_off[MM] = NN;

    // stage feat rows (coalesced float4)
    const float* fb = feat + ((size_t)k * DD + dbase) * NN;
    #pragma unroll
    for (int dd = 0; dd < DB; ++dd) {
        const float4* src = (const float4*)(fb + (size_t)dd * NN);
        float4* dst = (float4*)(s_feat + dd * NN);
        for (int i = tid; i < NN / 4; i += 128) dst[i] = src[i];
    }
    __syncthreads();

    // thread tid owns cluster tid: gather & accumulate in registers
    int st = s_off[tid];
    int en = s_off[tid + 1];
    float a0 = 0.f, a1 = 0.f, a2 = 0.f, a3 = 0.f;
    for (int p = st; p < en; ++p) {
        int pt = s_perm[p];
        a0 += s_feat[0 * NN + pt];
        a1 += s_feat[1 * NN + pt];
        a2 += s_feat[2 * NN + pt];
        a3 += s_feat[3 * NN + pt];
    }
    int s = k * MM + tid;
    float dn = fmaxf(g_counts[s], 1.0f);
    float4 o = make_float4(a0 / dn, a1 / dn, a2 / dn, a3 / dn);
    *(float4*)&out_cm[(size_t)s * DD + dbase] = o;
}

// ---------------- C1: per-segment norm -> scale factors ----------------
__global__ void k_norms(const float* __restrict__ cm) {
    int warp = (blockIdx.x * blockDim.x + threadIdx.x) >> 5;
    int lane = threadIdx.x & 31;
    if (warp >= SS) return;
    const float* row = cm + (size_t)warp * DD;
    float ss = 0.0f;
    #pragma unroll
    for (int i = lane; i < DD; i += 32) { float x = row[i]; ss += x * x; }
    #pragma unroll
    for (int o = 16; o > 0; o >>= 1) ss += __shfl_xor_sync(0xffffffffu, ss, o);
    if (lane == 0) {
        float invn = 1.0f / fmaxf(sqrtf(ss), EPSN);
        int cls = g_cls[warp];
        float maxden = fmaxf(__int_as_float(g_maxsize_bits), 1.0f);
        float w = cls ? (g_counts[warp] / maxden) : 0.0f;
        g_a[warp] = cls ? invn * w : 0.0f;
        g_b[warp] = cls ? invn : 0.0f;
    }
}

// ---------------- C2: v = cm^T a  (tiled column reduction) ----------------
__global__ __launch_bounds__(256)
void k_matvec_t(const float* __restrict__ cm) {
    __shared__ float s_a[256];
    int tid = threadIdx.x;
    int s0  = blockIdx.x * 256;
    s_a[tid] = g_a[s0 + tid];
    __syncthreads();
    float acc0 = 0.0f, acc1 = 0.0f;
    for (int r = 0; r < 256; ++r) {
        float av = s_a[r];
        if (av != 0.0f) {
            const float* row = cm + (size_t)(s0 + r) * DD;
            acc0 += row[tid] * av;
            if (tid < DD - 256) acc1 += row[256 + tid] * av;
        }
    }
    atomicAdd(&g_v[tid], acc0);
    if (tid < DD - 256) atomicAdd(&g_v[256 + tid], acc1);
}

// ---------------- D: sim_score[s] = b[s] * (cm[s] . v) ----------------
__global__ void k_sim(const float* __restrict__ cm,
                      float* __restrict__ out_sim) {
    int warp = (blockIdx.x * blockDim.x + threadIdx.x) >> 5;
    int lane = threadIdx.x & 31;
    if (warp >= SS) return;
    const float* row = cm + (size_t)warp * DD;
    float dot = 0.0f;
    #pragma unroll
    for (int i = lane; i < DD; i += 32) dot += row[i] * g_v[i];
    #pragma unroll
    for (int o = 16; o > 0; o >>= 1) dot += __shfl_xor_sync(0xffffffffu, dot, o);
    if (lane == 0) out_sim[warp] = g_b[warp] * dot;
}

// ---------------- E1: mean over class segments (single block, deterministic) ----------------
__global__ void k_mean(const float* __restrict__ sim) {
    __shared__ float s_sum[256];
    __shared__ float s_cnt[256];
    int tid = threadIdx.x;
    float sum = 0.0f, cnt = 0.0f;
    for (int s = tid; s < SS; s += 256) {
        if (g_cls[s]) { sum += sim[s]; cnt += 1.0f; }
    }
    s_sum[tid] = sum; s_cnt[tid] = cnt;
    __syncthreads();
    for (int o = 128; o > 0; o >>= 1) {
        if (tid < o) { s_sum[tid] += s_sum[tid + o]; s_cnt[tid] += s_cnt[tid + o]; }
        __syncthreads();
    }
    if (tid == 0) g_mean_score = s_sum[0] / fmaxf(s_cnt[0], 1.0f);
}

// ---------------- E2: clean mask ----------------
__global__ void k_clean(const float* __restrict__ sim,
                        float* __restrict__ out_clean) {
    int s = blockIdx.x * blockDim.x + threadIdx.x;
    if (s >= SS) return;
    float m = g_mean_score;
    out_clean[s] = ((sim[s] > m) && g_cls[s]) ? 1.0f : 0.0f;
}

// ---------------- launch ----------------
extern "C" void kernel_launch(void* const* d_in, const int* in_sizes, int n_in,
                              void* d_out, int out_size) {
    const float* feat  = (const float*)d_in[0];
    const float* label = (const float*)d_in[1];
    const int*   clab  = (const int*)d_in[2];
    float* out = (float*)d_out;
    float* out_cm    = out;                         // (S, D)
    float* out_sim   = out + (size_t)SS * DD;       // (S,)
    float* out_clean = out + (size_t)SS * DD + SS;  // (S,)

    k_zero<<<1, 320>>>();
    k_counts<<<KK, 256>>>(label, clab);
    k_gather<<<KK * NB, 128>>>(feat, out_cm);
    k_norms<<<(SS * 32 + 255) / 256, 256>>>(out_cm);
    k_matvec_t<<<SS / 256, 256>>>(out_cm);
    k_sim<<<(SS * 32 + 255) / 256, 256>>>(out_cm, out_sim);
    k_mean<<<1, 256>>>(out_sim);
    k_clean<<<SS / 256, 256>>>(out_sim, out_clean);
}

// round 3
// speedup vs baseline: 3.3796x; 1.5435x over previous
#include <cuda_runtime.h>
#include <cuda_bf16.h>
#include <math.h>

// Problem constants (fixed by setup_inputs)
#define KK   64
#define DD   320
#define NN   2048
#define MM   128
#define SS   (KK * MM)        // 8192 segments
#define DB   4                // dims per gather block
#define NB   (DD / DB)        // 80 dim-chunks
#define EPSN 1e-12f

// ---------------- device scratch (no allocations allowed) ----------------
__device__ float g_counts[SS];
__device__ int   g_cls[SS];
__device__ float g_b[SS];            // inv_norm * cls (for sim_score)
__device__ float g_v[DD];
__device__ int   g_maxsize_bits;
__device__ float g_mean_score;
__device__ int   g_off[SS];          // per-cloud exclusive prefix of cluster counts
__device__ int   g_perm[KK * NN];    // counting-sort permutation per cloud

// ---------------- Z: zero cross-kernel accumulators ----------------
__global__ void k_zero() {
    int t = threadIdx.x;
    if (t < DD) g_v[t] = 0.0f;
    if (t == 0) g_maxsize_bits = 0;
}

// ---------------- A: counts / label sums / class mask / offsets / perm ----------------
__global__ __launch_bounds__(256)
void k_counts(const float* __restrict__ label,
              const int*   __restrict__ clab) {
    __shared__ float s_cnt[MM];
    __shared__ float s_lbl[MM];
    __shared__ int   s_off[MM];
    __shared__ int   s_cur[MM];
    int k = blockIdx.x;
    int tid = threadIdx.x;
    if (tid < MM) { s_cnt[tid] = 0.0f; s_lbl[tid] = 0.0f; }
    __syncthreads();
    const int base = k * NN;
    for (int n = tid; n < NN; n += 256) {
        int cid = clab[base + n];
        atomicAdd(&s_cnt[cid], 1.0f);
        atomicAdd(&s_lbl[cid], label[base + n]);
    }
    __syncthreads();
    if (tid == 0) {
        int acc = 0;
        for (int m = 0; m < MM; ++m) { s_off[m] = acc; acc += (int)s_cnt[m]; }
    }
    __syncthreads();
    if (tid < MM) {
        int s = k * MM + tid;
        float c  = s_cnt[tid];
        float dn = fmaxf(c, 1.0f);
        float lm = s_lbl[tid] / dn;
        int cls  = (lm > 0.5f) && (c > 0.0f);
        g_counts[s] = c;
        g_cls[s]    = cls;
        g_off[s]    = s_off[tid];
        s_cur[tid]  = s_off[tid];
        float size  = cls ? c : 0.0f;
        atomicMax(&g_maxsize_bits, __float_as_int(size));  // monotone for non-neg floats
    }
    __syncthreads();
    for (int n = tid; n < NN; n += 256) {
        int cid = clab[base + n];
        int pos = atomicAdd(&s_cur[cid], 1);
        g_perm[base + pos] = n;
    }
}

// ---------------- B: staged gather -> cluster_means (NO atomics) ----------------
// grid = KK*NB blocks, 256 threads; block owns (cloud k, dims [dbase,dbase+4))
// thread (c, half): half=0/1 processes every other point of cluster c.
__global__ __launch_bounds__(256)
void k_gather(const float* __restrict__ feat,
              float*       __restrict__ out_cm) {
    __shared__ __align__(16) float s_feat[DB * NN];   // 32 KB
    __shared__ __align__(16) int   s_perm[NN];        // 8 KB
    __shared__ int   s_off[MM + 1];
    __shared__ float s_red[MM][DB];                   // 2 KB
    int k     = blockIdx.x / NB;
    int dbase = (blockIdx.x % NB) * DB;
    int tid   = threadIdx.x;

    // stage perm (coalesced int4)
    const int4* pg = (const int4*)(g_perm + k * NN);
    #pragma unroll
    for (int i = tid; i < NN / 4; i += 256) ((int4*)s_perm)[i] = pg[i];
    if (tid < MM) s_off[tid] = g_off[k * MM + tid];
    if (tid == 0) s_off[MM] = NN;

    // stage feat rows (coalesced float4)
    const float* fb = feat + ((size_t)k * DD + dbase) * NN;
    #pragma unroll
    for (int dd = 0; dd < DB; ++dd) {
        const float4* src = (const float4*)(fb + (size_t)dd * NN);
        float4* dst = (float4*)(s_feat + dd * NN);
        #pragma unroll
        for (int i = tid; i < NN / 4; i += 256) dst[i] = src[i];
    }
    __syncthreads();

    int c    = tid & (MM - 1);
    int half = tid >> 7;           // 0 or 1
    int st = s_off[c];
    int en = s_off[c + 1];
    float a0 = 0.f, a1 = 0.f, a2 = 0.f, a3 = 0.f;
    for (int p = st + half; p < en; p += 2) {
        int pt = s_perm[p];
        a0 += s_feat[0 * NN + pt];
        a1 += s_feat[1 * NN + pt];
        a2 += s_feat[2 * NN + pt];
        a3 += s_feat[3 * NN + pt];
    }
    if (half == 1) {
        s_red[c][0] = a0; s_red[c][1] = a1; s_red[c][2] = a2; s_red[c][3] = a3;
    }
    __syncthreads();
    if (half == 0) {
        a0 += s_red[c][0]; a1 += s_red[c][1]; a2 += s_red[c][2]; a3 += s_red[c][3];
        int s = k * MM + c;
        float dn = fmaxf(g_counts[s], 1.0f);
        float4 o = make_float4(a0 / dn, a1 / dn, a2 / dn, a3 / dn);
        *(float4*)&out_cm[(size_t)s * DD + dbase] = o;
    }
}

// ---------------- C (fused): norms + scale factors + v = fn^T w ----------------
// 64 blocks x 256 thr; warp per row (8 warps x 16 rows). Row stays in registers:
// norm via butterfly shuffle, then acc += row * a. Hierarchical v-reduction.
__global__ __launch_bounds__(256)
void k_normv(const float* __restrict__ cm) {
    __shared__ float s_v[DD];
    int tid  = threadIdx.x;
    int warp = tid >> 5;
    int lane = tid & 31;
    for (int i = tid; i < DD; i += 256) s_v[i] = 0.0f;
    __syncthreads();

    float acc[10];
    #pragma unroll
    for (int i = 0; i < 10; ++i) acc[i] = 0.0f;

    const int base = blockIdx.x * (SS / 64);   // 128 rows per block
    float maxden = fmaxf(__int_as_float(g_maxsize_bits), 1.0f);

    for (int r = warp; r < SS / 64; r += 8) {
        int s = base + r;
        const float* row = cm + (size_t)s * DD;
        float x[10];
        float ss = 0.0f;
        #pragma unroll
        for (int i = 0; i < 10; ++i) { x[i] = row[lane + 32 * i]; ss += x[i] * x[i]; }
        #pragma unroll
        for (int o = 16; o > 0; o >>= 1) ss += __shfl_xor_sync(0xffffffffu, ss, o);
        float invn = 1.0f / fmaxf(sqrtf(ss), EPSN);
        int cls = g_cls[s];
        float a = cls ? invn * (g_counts[s] / maxden) : 0.0f;
        if (lane == 0) g_b[s] = cls ? invn : 0.0f;
        #pragma unroll
        for (int i = 0; i < 10; ++i) acc[i] += x[i] * a;
    }

    // warp partials -> shared (conflict-free: distinct banks per lane)
    #pragma unroll
    for (int i = 0; i < 10; ++i) atomicAdd(&s_v[lane + 32 * i], acc[i]);
    __syncthreads();
    for (int i = tid; i < DD; i += 256) atomicAdd(&g_v[i], s_v[i]);
}

// ---------------- D: sim_score[s] = b[s] * (cm[s] . v) ----------------
__global__ __launch_bounds__(256)
void k_sim(const float* __restrict__ cm,
           float* __restrict__ out_sim) {
    __shared__ float s_v[DD];
    int tid = threadIdx.x;
    for (int i = tid; i < DD; i += 256) s_v[i] = g_v[i];
    __syncthreads();
    int warp = (blockIdx.x * 256 + tid) >> 5;
    int lane = tid & 31;
    if (warp >= SS) return;
    const float* row = cm + (size_t)warp * DD;
    float dot = 0.0f;
    #pragma unroll
    for (int i = 0; i < 10; ++i) dot += row[lane + 32 * i] * s_v[lane + 32 * i];
    #pragma unroll
    for (int o = 16; o > 0; o >>= 1) dot += __shfl_xor_sync(0xffffffffu, dot, o);
    if (lane == 0) out_sim[warp] = g_b[warp] * dot;
}

// ---------------- E1: mean over class segments (single block, deterministic) ----------------
__global__ void k_mean(const float* __restrict__ sim) {
    __shared__ float s_sum[256];
    __shared__ float s_cnt[256];
    int tid = threadIdx.x;
    float sum = 0.0f, cnt = 0.0f;
    for (int s = tid; s < SS; s += 256) {
        if (g_cls[s]) { sum += sim[s]; cnt += 1.0f; }
    }
    s_sum[tid] = sum; s_cnt[tid] = cnt;
    __syncthreads();
    for (int o = 128; o > 0; o >>= 1) {
        if (tid < o) { s_sum[tid] += s_sum[tid + o]; s_cnt[tid] += s_cnt[tid + o]; }
        __syncthreads();
    }
    if (tid == 0) g_mean_score = s_sum[0] / fmaxf(s_cnt[0], 1.0f);
}

// ---------------- E2: clean mask ----------------
__global__ void k_clean(const float* __restrict__ sim,
                        float* __restrict__ out_clean) {
    int s = blockIdx.x * blockDim.x + threadIdx.x;
    if (s >= SS) return;
    float m = g_mean_score;
    out_clean[s] = ((sim[s] > m) && g_cls[s]) ? 1.0f : 0.0f;
}

// ---------------- launch ----------------
extern "C" void kernel_launch(void* const* d_in, const int* in_sizes, int n_in,
                              void* d_out, int out_size) {
    const float* feat  = (const float*)d_in[0];
    const float* label = (const float*)d_in[1];
    const int*   clab  = (const int*)d_in[2];
    float* out = (float*)d_out;
    float* out_cm    = out;                         // (S, D)
    float* out_sim   = out + (size_t)SS * DD;       // (S,)
    float* out_clean = out + (size_t)SS * DD + SS;  // (S,)

    k_zero<<<1, 320>>>();
    k_counts<<<KK, 256>>>(label, clab);
    k_gather<<<KK * NB, 256>>>(feat, out_cm);
    k_normv<<<64, 256>>>(out_cm);
    k_sim<<<(SS * 32 + 255) / 256, 256>>>(out_cm, out_sim);
    k_mean<<<1, 256>>>(out_sim);
    k_clean<<<SS / 256, 256>>>(out_sim, out_clean);
}

// round 4
// speedup vs baseline: 4.2707x; 1.2637x over previous
#include <cuda_runtime.h>
#include <cuda_bf16.h>
#include <math.h>

// Problem constants (fixed by setup_inputs)
#define KK   64
#define DD   320
#define NN   2048
#define MM   128
#define SS   (KK * MM)        // 8192 segments
#define DB   4                // dims per gather block
#define NB   (DD / DB)        // 80 dim-chunks
#define EPSN 1e-12f
#define FBLK 256              // blocks in fused kernel (all co-resident)
#define RPB  (SS / FBLK)      // 32 rows per fused block
#define RPW  (RPB / 8)        // 4 rows per warp

// ---------------- device scratch (no allocations allowed) ----------------
__device__ float g_counts[SS];
__device__ int   g_cls[SS];
__device__ float g_v[DD];
__device__ int   g_maxsize_bits;
__device__ int   g_off[SS];          // per-cloud exclusive prefix of cluster counts
__device__ int   g_perm[KK * NN];    // counting-sort permutation per cloud
__device__ int   g_sync1;
__device__ int   g_sync2;
__device__ float g_msum;
__device__ float g_mcnt;

// ---------------- Z: zero cross-kernel accumulators ----------------
__global__ void k_zero() {
    int t = threadIdx.x;
    if (t < DD) g_v[t] = 0.0f;
    if (t == 0) { g_maxsize_bits = 0; g_sync1 = 0; g_sync2 = 0; g_msum = 0.0f; g_mcnt = 0.0f; }
}

// ---------------- A: counts / label sums / class mask / offsets / perm ----------------
__global__ __launch_bounds__(256)
void k_counts(const float* __restrict__ label,
              const int*   __restrict__ clab) {
    __shared__ float s_cnt[MM];
    __shared__ float s_lbl[MM];
    __shared__ int   s_off[MM];
    __shared__ int   s_cur[MM];
    int k = blockIdx.x;
    int tid = threadIdx.x;
    int lane = tid & 31;
    if (tid < MM) { s_cnt[tid] = 0.0f; s_lbl[tid] = 0.0f; }
    __syncthreads();
    const int base = k * NN;
    for (int n = tid; n < NN; n += 256) {
        int cid = clab[base + n];
        atomicAdd(&s_cnt[cid], 1.0f);
        atomicAdd(&s_lbl[cid], label[base + n]);
    }
    __syncthreads();
    // warp-parallel exclusive scan of 128 counts (warp 0)
    if (tid < 32) {
        int c0 = (int)s_cnt[lane * 4 + 0];
        int c1 = (int)s_cnt[lane * 4 + 1];
        int c2 = (int)s_cnt[lane * 4 + 2];
        int c3 = (int)s_cnt[lane * 4 + 3];
        int t  = c0 + c1 + c2 + c3;
        int pre = t;
        #pragma unroll
        for (int o = 1; o < 32; o <<= 1) {
            int nb = __shfl_up_sync(0xffffffffu, pre, o);
            if (lane >= o) pre += nb;
        }
        int ex = pre - t;                   // exclusive prefix of this lane's group
        s_off[lane * 4 + 0] = ex;
        s_off[lane * 4 + 1] = ex + c0;
        s_off[lane * 4 + 2] = ex + c0 + c1;
        s_off[lane * 4 + 3] = ex + c0 + c1 + c2;
    }
    __syncthreads();
    if (tid < MM) {
        int s = k * MM + tid;
        float c  = s_cnt[tid];
        float dn = fmaxf(c, 1.0f);
        float lm = s_lbl[tid] / dn;
        int cls  = (lm > 0.5f) && (c > 0.0f);
        g_counts[s] = c;
        g_cls[s]    = cls;
        g_off[s]    = s_off[tid];
        s_cur[tid]  = s_off[tid];
        float size  = cls ? c : 0.0f;
        atomicMax(&g_maxsize_bits, __float_as_int(size));  // monotone for non-neg floats
    }
    __syncthreads();
    for (int n = tid; n < NN; n += 256) {
        int cid = clab[base + n];
        int pos = atomicAdd(&s_cur[cid], 1);
        g_perm[base + pos] = n;
    }
}

// ---------------- B: staged gather -> cluster_means (NO atomics) ----------------
__global__ __launch_bounds__(256)
void k_gather(const float* __restrict__ feat,
              float*       __restrict__ out_cm) {
    __shared__ __align__(16) float s_feat[DB * NN];   // 32 KB
    __shared__ __align__(16) int   s_perm[NN];        // 8 KB
    __shared__ int   s_off[MM + 1];
    __shared__ float s_red[MM][DB];                   // 2 KB
    int k     = blockIdx.x / NB;
    int dbase = (blockIdx.x % NB) * DB;
    int tid   = threadIdx.x;

    const int4* pg = (const int4*)(g_perm + k * NN);
    #pragma unroll
    for (int i = tid; i < NN / 4; i += 256) ((int4*)s_perm)[i] = pg[i];
    if (tid < MM) s_off[tid] = g_off[k * MM + tid];
    if (tid == 0) s_off[MM] = NN;

    const float* fb = feat + ((size_t)k * DD + dbase) * NN;
    #pragma unroll
    for (int dd = 0; dd < DB; ++dd) {
        const float4* src = (const float4*)(fb + (size_t)dd * NN);
        float4* dst = (float4*)(s_feat + dd * NN);
        #pragma unroll
        for (int i = tid; i < NN / 4; i += 256) dst[i] = src[i];
    }
    __syncthreads();

    int c    = tid & (MM - 1);
    int half = tid >> 7;
    int st = s_off[c];
    int en = s_off[c + 1];
    float a0 = 0.f, a1 = 0.f, a2 = 0.f, a3 = 0.f;
    for (int p = st + half; p < en; p += 2) {
        int pt = s_perm[p];
        a0 += s_feat[0 * NN + pt];
        a1 += s_feat[1 * NN + pt];
        a2 += s_feat[2 * NN + pt];
        a3 += s_feat[3 * NN + pt];
    }
    if (half == 1) {
        s_red[c][0] = a0; s_red[c][1] = a1; s_red[c][2] = a2; s_red[c][3] = a3;
    }
    __syncthreads();
    if (half == 0) {
        a0 += s_red[c][0]; a1 += s_red[c][1]; a2 += s_red[c][2]; a3 += s_red[c][3];
        int s = k * MM + c;
        float dn = fmaxf(g_counts[s], 1.0f);
        float4 o = make_float4(a0 / dn, a1 / dn, a2 / dn, a3 / dn);
        *(float4*)&out_cm[(size_t)s * DD + dbase] = o;
    }
}

// ---------------- F (fused): norms + v + sim + mean + clean ----------------
// 256 blocks x 256 thr, ALL co-resident (<=~96 regs). Rows live in registers
// across two grid-wide syncs, so cluster_means is read exactly once.
__global__ __launch_bounds__(256)
void k_fused(const float* __restrict__ cm,
             float* __restrict__ out_sim,
             float* __restrict__ out_clean) {
    __shared__ float s_v[DD];
    __shared__ float s_ms[8];
    __shared__ float s_mc[8];
    int tid  = threadIdx.x;
    int warp = tid >> 5;
    int lane = tid & 31;
    for (int i = tid; i < DD; i += 256) s_v[i] = 0.0f;
    __syncthreads();

    const int base = blockIdx.x * RPB + warp * RPW;
    float maxden = fmaxf(__int_as_float(g_maxsize_bits), 1.0f);

    float x[RPW][10];
    float bfac[RPW];
    int   cls[RPW];
    float acc[10];
    #pragma unroll
    for (int j = 0; j < 10; ++j) acc[j] = 0.0f;

    #pragma unroll
    for (int i = 0; i < RPW; ++i) {
        int s = base + i;
        const float* row = cm + (size_t)s * DD;
        float ss = 0.0f;
        #pragma unroll
        for (int j = 0; j < 10; ++j) { x[i][j] = row[lane + 32 * j]; ss += x[i][j] * x[i][j]; }
        #pragma unroll
        for (int o = 16; o > 0; o >>= 1) ss += __shfl_xor_sync(0xffffffffu, ss, o);
        float invn = 1.0f / fmaxf(sqrtf(ss), EPSN);
        cls[i]  = g_cls[s];
        bfac[i] = cls[i] ? invn : 0.0f;
        float a = cls[i] ? invn * (g_counts[s] / maxden) : 0.0f;
        #pragma unroll
        for (int j = 0; j < 10; ++j) acc[j] += x[i][j] * a;
    }

    // block-level v: warp partials to smem (distinct banks), then global atomics
    #pragma unroll
    for (int j = 0; j < 10; ++j) atomicAdd(&s_v[lane + 32 * j], acc[j]);
    __syncthreads();
    for (int i = tid; i < DD; i += 256) atomicAdd(&g_v[i], s_v[i]);
    __threadfence();
    __syncthreads();

    // ---- grid sync #1 ----
    if (tid == 0) {
        atomicAdd(&g_sync1, 1);
        while (*(volatile int*)&g_sync1 < FBLK) __nanosleep(64);
        __threadfence();
    }
    __syncthreads();

    // v from L2 (written by atomics), rows still in registers
    float vv[10];
    #pragma unroll
    for (int j = 0; j < 10; ++j) vv[j] = __ldcg(&g_v[lane + 32 * j]);

    float sim[RPW];
    float psum = 0.0f, pcnt = 0.0f;
    #pragma unroll
    for (int i = 0; i < RPW; ++i) {
        float dot = 0.0f;
        #pragma unroll
        for (int j = 0; j < 10; ++j) dot += x[i][j] * vv[j];
        #pragma unroll
        for (int o = 16; o > 0; o >>= 1) dot += __shfl_xor_sync(0xffffffffu, dot, o);
        sim[i] = bfac[i] * dot;
        if (lane == 0) {
            out_sim[base + i] = sim[i];
            if (cls[i]) { psum += sim[i]; pcnt += 1.0f; }
        }
    }
    if (lane == 0) { s_ms[warp] = psum; s_mc[warp] = pcnt; }
    __syncthreads();
    if (tid == 0) {
        float bs = 0.0f, bc = 0.0f;
        #pragma unroll
        for (int w = 0; w < 8; ++w) { bs += s_ms[w]; bc += s_mc[w]; }
        atomicAdd(&g_msum, bs);
        atomicAdd(&g_mcnt, bc);
        __threadfence();
        // ---- grid sync #2 ----
        atomicAdd(&g_sync2, 1);
        while (*(volatile int*)&g_sync2 < FBLK) __nanosleep(64);
        __threadfence();
    }
    __syncthreads();

    float mean = __ldcg(&g_msum) / fmaxf(__ldcg(&g_mcnt), 1.0f);
    if (lane == 0) {
        #pragma unroll
        for (int i = 0; i < RPW; ++i)
            out_clean[base + i] = ((sim[i] > mean) && cls[i]) ? 1.0f : 0.0f;
    }
}

// ---------------- launch ----------------
extern "C" void kernel_launch(void* const* d_in, const int* in_sizes, int n_in,
                              void* d_out, int out_size) {
    const float* feat  = (const float*)d_in[0];
    const float* label = (const float*)d_in[1];
    const int*   clab  = (const int*)d_in[2];
    float* out = (float*)d_out;
    float* out_cm    = out;                         // (S, D)
    float* out_sim   = out + (size_t)SS * DD;       // (S,)
    float* out_clean = out + (size_t)SS * DD + SS;  // (S,)

    k_zero<<<1, 320>>>();
    k_counts<<<KK, 256>>>(label, clab);
    k_gather<<<KK * NB, 256>>>(feat, out_cm);
    k_fused<<<FBLK, 256>>>(out_cm, out_sim, out_clean);
}

// round 5
// speedup vs baseline: 4.4585x; 1.0440x over previous
#include <cuda_runtime.h>
#include <cuda_bf16.h>
#include <math.h>

#define KK   64
#define DD   320
#define NN   2048
#define MM   128
#define SS   (KK * MM)        // 8192
#define DB   4                // dims per gather block (contiguous chunk!)
#define NB   (DD / DB)        // 80
#define EPSN 1e-12f
#define FBLK 256
#define RPB  (SS / FBLK)      // 32 rows / fused block
#define RPW  (RPB / 8)        // 4 rows / warp

// ---------------- device scratch ----------------
__device__ float g_counts[SS];
__device__ int   g_cls[SS];
__device__ __align__(16) float g_v[DD];
__device__ int   g_maxsize_bits;
__device__ int   g_off[SS];
__device__ int   g_perm[KK * NN];
__device__ int   g_sync1;
__device__ int   g_sync2;
__device__ float g_msum;
__device__ float g_mcnt;

// ---------------- Z ----------------
__global__ void k_zero() {
    int t = threadIdx.x;
    if (t < DD) g_v[t] = 0.0f;
    if (t == 0) { g_maxsize_bits = 0; g_sync1 = 0; g_sync2 = 0; g_msum = 0.0f; g_mcnt = 0.0f; }
}

// ---------------- A: counts / offsets / perm ----------------
__global__ __launch_bounds__(256)
void k_counts(const float* __restrict__ label,
              const int*   __restrict__ clab) {
    __shared__ float s_cnt[MM];
    __shared__ float s_lbl[MM];
    __shared__ int   s_off[MM];
    __shared__ int   s_cur[MM];
    int k = blockIdx.x;
    int tid = threadIdx.x;
    int lane = tid & 31;
    if (tid < MM) { s_cnt[tid] = 0.0f; s_lbl[tid] = 0.0f; }
    __syncthreads();
    const int base = k * NN;
    const int4*   cg = (const int4*)(clab + base);
    const float4* lg = (const float4*)(label + base);
    int4 c4[2]; float4 l4[2];
    #pragma unroll
    for (int i = 0; i < 2; ++i) {
        c4[i] = cg[tid + 256 * i];
        l4[i] = lg[tid + 256 * i];
        atomicAdd(&s_cnt[c4[i].x], 1.0f); atomicAdd(&s_lbl[c4[i].x], l4[i].x);
        atomicAdd(&s_cnt[c4[i].y], 1.0f); atomicAdd(&s_lbl[c4[i].y], l4[i].y);
        atomicAdd(&s_cnt[c4[i].z], 1.0f); atomicAdd(&s_lbl[c4[i].z], l4[i].z);
        atomicAdd(&s_cnt[c4[i].w], 1.0f); atomicAdd(&s_lbl[c4[i].w], l4[i].w);
    }
    __syncthreads();
    // warp-parallel exclusive scan of 128 counts (warp 0)
    if (tid < 32) {
        int e0 = (int)s_cnt[lane * 4 + 0];
        int e1 = (int)s_cnt[lane * 4 + 1];
        int e2 = (int)s_cnt[lane * 4 + 2];
        int e3 = (int)s_cnt[lane * 4 + 3];
        int t  = e0 + e1 + e2 + e3;
        int pre = t;
        #pragma unroll
        for (int o = 1; o < 32; o <<= 1) {
            int nb = __shfl_up_sync(0xffffffffu, pre, o);
            if (lane >= o) pre += nb;
        }
        int ex = pre - t;
        s_off[lane * 4 + 0] = ex;
        s_off[lane * 4 + 1] = ex + e0;
        s_off[lane * 4 + 2] = ex + e0 + e1;
        s_off[lane * 4 + 3] = ex + e0 + e1 + e2;
    }
    __syncthreads();
    if (tid < MM) {
        int s = k * MM + tid;
        float c  = s_cnt[tid];
        float dn = fmaxf(c, 1.0f);
        float lm = s_lbl[tid] / dn;
        int cls  = (lm > 0.5f) && (c > 0.0f);
        g_counts[s] = c;
        g_cls[s]    = cls;
        g_off[s]    = s_off[tid];
        s_cur[tid]  = s_off[tid];
        float size  = cls ? c : 0.0f;
        atomicMax(&g_maxsize_bits, __float_as_int(size));
    }
    __syncthreads();
    #pragma unroll
    for (int i = 0; i < 2; ++i) {
        int n0 = (tid + 256 * i) * 4;
        int p;
        p = atomicAdd(&s_cur[c4[i].x], 1); g_perm[base + p] = n0 + 0;
        p = atomicAdd(&s_cur[c4[i].y], 1); g_perm[base + p] = n0 + 1;
        p = atomicAdd(&s_cur[c4[i].z], 1); g_perm[base + p] = n0 + 2;
        p = atomicAdd(&s_cur[c4[i].w], 1); g_perm[base + p] = n0 + 3;
    }
}

// ---------------- B: staged gather (512 thr, 4-way split per cluster) ----------------
__global__ __launch_bounds__(512)
void k_gather(const float* __restrict__ feat,
              float*       __restrict__ out_cm) {
    __shared__ __align__(16) float s_feat[DB * NN];       // 32 KB
    __shared__ __align__(16) int   s_perm[NN];            // 8 KB
    __shared__ int   s_off[MM + 1];
    __shared__ float s_red[3][MM][DB];                    // 6 KB
    int k     = blockIdx.x / NB;
    int dbase = (blockIdx.x % NB) * DB;
    int tid   = threadIdx.x;

    // perm: 512 int4, one per thread
    ((int4*)s_perm)[tid] = ((const int4*)(g_perm + k * NN))[tid];
    if (tid < MM) s_off[tid] = g_off[k * MM + tid];
    if (tid == 0) s_off[MM] = NN;

    // feat chunk is one contiguous 32 KB region: plain float4 copy
    const float4* fb4 = (const float4*)(feat + ((size_t)k * DD + dbase) * NN);
    float4* sf4 = (float4*)s_feat;
    #pragma unroll
    for (int i = tid; i < DB * NN / 4; i += 512) sf4[i] = fb4[i];
    __syncthreads();

    int c = tid & (MM - 1);
    int q = tid >> 7;                 // 0..3
    int st = s_off[c];
    int en = s_off[c + 1];
    float a0 = 0.f, a1 = 0.f, a2 = 0.f, a3 = 0.f;
    for (int p = st + q; p < en; p += 4) {
        int pt = s_perm[p];
        a0 += s_feat[0 * NN + pt];
        a1 += s_feat[1 * NN + pt];
        a2 += s_feat[2 * NN + pt];
        a3 += s_feat[3 * NN + pt];
    }
    if (q) {
        s_red[q - 1][c][0] = a0; s_red[q - 1][c][1] = a1;
        s_red[q - 1][c][2] = a2; s_red[q - 1][c][3] = a3;
    }
    __syncthreads();
    if (q == 0) {
        #pragma unroll
        for (int r = 0; r < 3; ++r) {
            a0 += s_red[r][c][0]; a1 += s_red[r][c][1];
            a2 += s_red[r][c][2]; a3 += s_red[r][c][3];
        }
        int s = k * MM + c;
        float dn = fmaxf(g_counts[s], 1.0f);
        float4 o = make_float4(a0 / dn, a1 / dn, a2 / dn, a3 / dn);
        *(float4*)&out_cm[(size_t)s * DD + dbase] = o;
    }
}

// ---------------- F: fused norms + v + sim + mean + clean (float4) ----------------
__global__ void __launch_bounds__(256, 2)
k_fused(const float* __restrict__ cm,
        float* __restrict__ out_sim,
        float* __restrict__ out_clean) {
    __shared__ float s_v[DD];
    __shared__ float s_ms[8];
    __shared__ float s_mc[8];
    int tid  = threadIdx.x;
    int warp = tid >> 5;
    int lane = tid & 31;
    for (int i = tid; i < DD; i += 256) s_v[i] = 0.0f;
    __syncthreads();

    const int base = blockIdx.x * RPB + warp * RPW;
    float maxden = fmaxf(__int_as_float(g_maxsize_bits), 1.0f);
    const float4 z4 = make_float4(0.f, 0.f, 0.f, 0.f);

    float4 x[RPW][3];
    float bfac[RPW];
    int   cls[RPW];
    float4 acc0 = z4, acc1 = z4, acc2 = z4;

    #pragma unroll
    for (int i = 0; i < RPW; ++i) {
        int s = base + i;
        const float4* row = (const float4*)(cm + (size_t)s * DD);
        x[i][0] = row[lane];
        x[i][1] = row[32 + lane];
        x[i][2] = (lane < 16) ? row[64 + lane] : z4;
        float ss = x[i][0].x * x[i][0].x + x[i][0].y * x[i][0].y + x[i][0].z * x[i][0].z + x[i][0].w * x[i][0].w
                 + x[i][1].x * x[i][1].x + x[i][1].y * x[i][1].y + x[i][1].z * x[i][1].z + x[i][1].w * x[i][1].w
                 + x[i][2].x * x[i][2].x + x[i][2].y * x[i][2].y + x[i][2].z * x[i][2].z + x[i][2].w * x[i][2].w;
        #pragma unroll
        for (int o = 16; o > 0; o >>= 1) ss += __shfl_xor_sync(0xffffffffu, ss, o);
        float invn = 1.0f / fmaxf(sqrtf(ss), EPSN);
        cls[i]  = g_cls[s];
        bfac[i] = cls[i] ? invn : 0.0f;
        float a = cls[i] ? invn * (g_counts[s] / maxden) : 0.0f;
        acc0.x += x[i][0].x * a; acc0.y += x[i][0].y * a; acc0.z += x[i][0].z * a; acc0.w += x[i][0].w * a;
        acc1.x += x[i][1].x * a; acc1.y += x[i][1].y * a; acc1.z += x[i][1].z * a; acc1.w += x[i][1].w * a;
        acc2.x += x[i][2].x * a; acc2.y += x[i][2].y * a; acc2.z += x[i][2].z * a; acc2.w += x[i][2].w * a;
    }

    // block-level v
    atomicAdd(&s_v[4 * lane + 0], acc0.x); atomicAdd(&s_v[4 * lane + 1], acc0.y);
    atomicAdd(&s_v[4 * lane + 2], acc0.z); atomicAdd(&s_v[4 * lane + 3], acc0.w);
    atomicAdd(&s_v[128 + 4 * lane + 0], acc1.x); atomicAdd(&s_v[128 + 4 * lane + 1], acc1.y);
    atomicAdd(&s_v[128 + 4 * lane + 2], acc1.z); atomicAdd(&s_v[128 + 4 * lane + 3], acc1.w);
    if (lane < 16) {
        atomicAdd(&s_v[256 + 4 * lane + 0], acc2.x); atomicAdd(&s_v[256 + 4 * lane + 1], acc2.y);
        atomicAdd(&s_v[256 + 4 * lane + 2], acc2.z); atomicAdd(&s_v[256 + 4 * lane + 3], acc2.w);
    }
    __syncthreads();
    for (int i = tid; i < DD; i += 256) atomicAdd(&g_v[i], s_v[i]);
    __threadfence();
    __syncthreads();

    // grid sync #1
    if (tid == 0) {
        atomicAdd(&g_sync1, 1);
        while (*(volatile int*)&g_sync1 < FBLK) __nanosleep(64);
        __threadfence();
    }
    __syncthreads();

    const float4* gv4 = (const float4*)g_v;
    float4 v0 = __ldcg(gv4 + lane);
    float4 v1 = __ldcg(gv4 + 32 + lane);
    float4 v2 = (lane < 16) ? __ldcg(gv4 + 64 + lane) : z4;

    float sim[RPW];
    float psum = 0.0f, pcnt = 0.0f;
    #pragma unroll
    for (int i = 0; i < RPW; ++i) {
        float dot = x[i][0].x * v0.x + x[i][0].y * v0.y + x[i][0].z * v0.z + x[i][0].w * v0.w
                  + x[i][1].x * v1.x + x[i][1].y * v1.y + x[i][1].z * v1.z + x[i][1].w * v1.w
                  + x[i][2].x * v2.x + x[i][2].y * v2.y + x[i][2].z * v2.z + x[i][2].w * v2.w;
        #pragma unroll
        for (int o = 16; o > 0; o >>= 1) dot += __shfl_xor_sync(0xffffffffu, dot, o);
        sim[i] = bfac[i] * dot;
        if (lane == 0) {
            out_sim[base + i] = sim[i];
            if (cls[i]) { psum += sim[i]; pcnt += 1.0f; }
        }
    }
    if (lane == 0) { s_ms[warp] = psum; s_mc[warp] = pcnt; }
    __syncthreads();
    if (tid == 0) {
        float bs = 0.0f, bc = 0.0f;
        #pragma unroll
        for (int w = 0; w < 8; ++w) { bs += s_ms[w]; bc += s_mc[w]; }
        atomicAdd(&g_msum, bs);
        atomicAdd(&g_mcnt, bc);
        __threadfence();
        atomicAdd(&g_sync2, 1);
        while (*(volatile int*)&g_sync2 < FBLK) __nanosleep(64);
        __threadfence();
    }
    __syncthreads();

    float mean = __ldcg(&g_msum) / fmaxf(__ldcg(&g_mcnt), 1.0f);
    if (lane == 0) {
        #pragma unroll
        for (int i = 0; i < RPW; ++i)
            out_clean[base + i] = ((sim[i] > mean) && cls[i]) ? 1.0f : 0.0f;
    }
}

// ---------------- launch ----------------
extern "C" void kernel_launch(void* const* d_in, const int* in_sizes, int n_in,
                              void* d_out, int out_size) {
    const float* feat  = (const float*)d_in[0];
    const float* label = (const float*)d_in[1];
    const int*   clab  = (const int*)d_in[2];
    float* out = (float*)d_out;
    float* out_cm    = out;
    float* out_sim   = out + (size_t)SS * DD;
    float* out_clean = out + (size_t)SS * DD + SS;

    k_zero<<<1, 320>>>();
    k_counts<<<KK, 256>>>(label, clab);
    k_gather<<<KK * NB, 512>>>(feat, out_cm);
    k_fused<<<FBLK, 256>>>(out_cm, out_sim, out_clean);
}